// round 14
// baseline (speedup 1.0000x reference)
#include <cuda_runtime.h>
#include <cuda_fp16.h>
#include <math.h>
#include <float.h>

#define NN 80000
#define EE 1280000
#define GG 64
#define CINC 128
#define DD 64
#define NHID 5
#define NB_SCAN ((NN + 1023) / 1024)

typedef unsigned long long u64t;

__device__ __forceinline__ u64t fma2(u64t a, u64t b, u64t c) {
    u64t d;
    asm("fma.rn.f32x2 %0, %1, %2, %3;" : "=l"(d) : "l"(a), "l"(b), "l"(c));
    return d;
}
__device__ __forceinline__ float2 h22f2(unsigned u) {
    return __half22float2(*reinterpret_cast<__half2*>(&u));
}

// ---------------- scratch ----------------
__device__ int     g_deg[NN];
__device__ float   g_dinv[NN];
__device__ int     g_rowptr[NN + 1];
__device__ int     g_eoff[EE];
__device__ int2    g_edge[EE];         // {src, wnorm bits}
__device__ __half2 g_h0h[NN * 32];     // GEMM output (fp16, gather source)
__device__ __half2 g_h1h[NN * 32];     // aggregation output (fp16)
__device__ int     g_bsum[NB_SCAN];
__device__ int     g_boff[NB_SCAN];
__device__ int     g_scan_done;

// ---------------- CSR build ----------------
__global__ void zero_deg_kernel() {
    int i = blockIdx.x * blockDim.x + threadIdx.x;
    if (i < NN) g_deg[i] = 0;
    if (i == 0) g_scan_done = 0;
}

__global__ void count_deg_kernel(const int* __restrict__ ei) {
    int e = blockIdx.x * blockDim.x + threadIdx.x;
    if (e < EE) g_eoff[e] = atomicAdd(&g_deg[ei[EE + e]], 1);
}

__global__ void scanAB_kernel() {
    __shared__ int sh[1024];
    int gid = blockIdx.x * 1024 + threadIdx.x;
    int v = (gid < NN) ? g_deg[gid] : 0;
    if (gid < NN) g_dinv[gid] = rsqrtf((float)(v + 1));
    sh[threadIdx.x] = v;
    __syncthreads();
    #pragma unroll
    for (int off = 1; off < 1024; off <<= 1) {
        int t = (threadIdx.x >= off) ? sh[threadIdx.x - off] : 0;
        __syncthreads();
        sh[threadIdx.x] += t;
        __syncthreads();
    }
    if (gid < NN) g_rowptr[gid] = sh[threadIdx.x] - v;
    if (threadIdx.x == 1023) g_bsum[blockIdx.x] = sh[1023];

    __shared__ int s_last;
    __threadfence();
    if (threadIdx.x == 0)
        s_last = (atomicAdd(&g_scan_done, 1) == NB_SCAN - 1);
    __syncthreads();
    if (s_last) {
        int t = threadIdx.x;
        int bv = (t < NB_SCAN) ? g_bsum[t] : 0;
        if (t < 128) sh[t] = bv;
        __syncthreads();
        #pragma unroll
        for (int off = 1; off < 128; off <<= 1) {
            int u = (t >= off && t < 128) ? sh[t - off] : 0;
            __syncthreads();
            if (t < 128) sh[t] += u;
            __syncthreads();
        }
        if (t < NB_SCAN) g_boff[t] = sh[t] - bv;
    }
}

__global__ void scanC_kernel() {
    int gid = blockIdx.x * 1024 + threadIdx.x;
    if (gid < NN)
        g_rowptr[gid] += g_boff[blockIdx.x];
    if (gid == 0) g_rowptr[NN] = EE;
}

__global__ void scatter_kernel(const int* __restrict__ ei) {
    int e = blockIdx.x * blockDim.x + threadIdx.x;
    if (e < EE) {
        int s = ei[e];
        int d = ei[EE + e];
        int pos = g_rowptr[d] + g_eoff[e];
        float w = g_dinv[s] * g_dinv[d];
        g_edge[pos] = make_int2(s, __float_as_int(w));
    }
}

// ------ Tiled GEMM: g_h0h[N,64](fp16) = A[N,K] @ W[K,64] ------------------
// 256 threads = 8 warps; warp = 16 rows x 64 cols; lane = 16 rows x 2 cols.
// smem: Ws [K][64] fp32 (lane LDS.64, conflict-free);
//       Xt [K][66 u64] row-pair packed f32x2 (uniform LDS.128 broadcast).
#define XT_LD 66
template <int K, bool FROM_EXT>
__global__ __launch_bounds__(256) void gemm_kernel(const float* __restrict__ X,
                                                   const float* __restrict__ W) {
    extern __shared__ char smem_raw[];
    float* Ws = reinterpret_cast<float*>(smem_raw);
    u64t*  Xt = reinterpret_cast<u64t*>(smem_raw + (size_t)K * 256);

    int tid = threadIdx.x;

    // W: coalesced copy
    #pragma unroll
    for (int i = tid; i < K * 64; i += 256) Ws[i] = W[i];

    // X: load + transpose into row-pair-packed layout
    if (FROM_EXT) {
        const float* xb = X + (size_t)blockIdx.x * 128 * K;
        #pragma unroll
        for (int i = tid; i < 128 * K; i += 256) {
            int r = i / K, k = i - r * K;
            reinterpret_cast<float*>(Xt + (size_t)k * XT_LD + (r >> 1))[r & 1] = xb[i];
        }
    } else {
        const uint4* ab = reinterpret_cast<const uint4*>(g_h1h) +
                          (size_t)blockIdx.x * 128 * 8;   // 8 uint4 per 64-half row
        #pragma unroll
        for (int i = tid; i < 128 * 8; i += 256) {
            int r = i >> 3, c8 = i & 7;
            uint4 v = ab[i];
            float2 f0 = h22f2(v.x), f1 = h22f2(v.y), f2 = h22f2(v.z), f3 = h22f2(v.w);
            int k0 = c8 * 8;
            int rp = r >> 1, rb = r & 1;
            reinterpret_cast<float*>(Xt + (size_t)(k0 + 0) * XT_LD + rp)[rb] = f0.x;
            reinterpret_cast<float*>(Xt + (size_t)(k0 + 1) * XT_LD + rp)[rb] = f0.y;
            reinterpret_cast<float*>(Xt + (size_t)(k0 + 2) * XT_LD + rp)[rb] = f1.x;
            reinterpret_cast<float*>(Xt + (size_t)(k0 + 3) * XT_LD + rp)[rb] = f1.y;
            reinterpret_cast<float*>(Xt + (size_t)(k0 + 4) * XT_LD + rp)[rb] = f2.x;
            reinterpret_cast<float*>(Xt + (size_t)(k0 + 5) * XT_LD + rp)[rb] = f2.y;
            reinterpret_cast<float*>(Xt + (size_t)(k0 + 6) * XT_LD + rp)[rb] = f3.x;
            reinterpret_cast<float*>(Xt + (size_t)(k0 + 7) * XT_LD + rp)[rb] = f3.y;
        }
    }
    __syncthreads();

    int lane = tid & 31, warp = tid >> 5;

    u64t acc[16];   // acc[2*rp + c]: rp=0..7 (row pairs), c=0..1 (cols 2*lane+c)
    #pragma unroll
    for (int j = 0; j < 16; j++) acc[j] = 0ull;

    #pragma unroll 4
    for (int k = 0; k < K; k++) {
        // W: lane's two columns, contiguous 8B -> conflict-free LDS.64
        u64t w2 = *reinterpret_cast<const u64t*>(Ws + k * 64 + 2 * lane);
        unsigned wl, wh;
        asm("mov.b64 {%0, %1}, %2;" : "=r"(wl), "=r"(wh) : "l"(w2));
        u64t wd0, wd1;
        asm("mov.b64 %0, {%1, %1};" : "=l"(wd0) : "r"(wl));
        asm("mov.b64 %0, {%1, %1};" : "=l"(wd1) : "r"(wh));

        // X: 8 row pairs, uniform broadcast LDS.128 x4
        const ulonglong2* xp = reinterpret_cast<const ulonglong2*>(
            Xt + (size_t)k * XT_LD + warp * 8);
        ulonglong2 xa = xp[0], xb2 = xp[1], xc = xp[2], xd = xp[3];

        acc[0]  = fma2(xa.x,  wd0, acc[0]);  acc[1]  = fma2(xa.x,  wd1, acc[1]);
        acc[2]  = fma2(xa.y,  wd0, acc[2]);  acc[3]  = fma2(xa.y,  wd1, acc[3]);
        acc[4]  = fma2(xb2.x, wd0, acc[4]);  acc[5]  = fma2(xb2.x, wd1, acc[5]);
        acc[6]  = fma2(xb2.y, wd0, acc[6]);  acc[7]  = fma2(xb2.y, wd1, acc[7]);
        acc[8]  = fma2(xc.x,  wd0, acc[8]);  acc[9]  = fma2(xc.x,  wd1, acc[9]);
        acc[10] = fma2(xc.y,  wd0, acc[10]); acc[11] = fma2(xc.y,  wd1, acc[11]);
        acc[12] = fma2(xd.x,  wd0, acc[12]); acc[13] = fma2(xd.x,  wd1, acc[13]);
        acc[14] = fma2(xd.y,  wd0, acc[14]); acc[15] = fma2(xd.y,  wd1, acc[15]);
    }

    // epilogue: rows warp*16 + 2*rp (+1), cols {2*lane, 2*lane+1} -> half2
    size_t rowbase = (size_t)blockIdx.x * 128 + warp * 16;
    #pragma unroll
    for (int rp = 0; rp < 8; rp++) {
        unsigned l0, h0, l1, h1;
        asm("mov.b64 {%0, %1}, %2;" : "=r"(l0), "=r"(h0) : "l"(acc[2 * rp]));
        asm("mov.b64 {%0, %1}, %2;" : "=r"(l1), "=r"(h1) : "l"(acc[2 * rp + 1]));
        size_t r0 = rowbase + 2 * rp;
        g_h0h[r0 * 32 + lane] =
            __floats2half2_rn(__uint_as_float(l0), __uint_as_float(l1));
        g_h0h[(r0 + 1) * 32 + lane] =
            __floats2half2_rn(__uint_as_float(h0), __uint_as_float(h1));
    }
}

// ------ aggregation: HALF-warp per node, fp16 in/out -----------------------
__global__ void aggregate_kernel(const float* __restrict__ bias, int relu) {
    int warp = blockIdx.x * (blockDim.x >> 5) + (threadIdx.x >> 5);
    int half = (threadIdx.x >> 4) & 1;
    int hl   = threadIdx.x & 15;
    int node = warp * 2 + half;
    if (node >= NN) return;

    const uint2* h0 = reinterpret_cast<const uint2*>(g_h0h);

    float dn = g_dinv[node];
    float sw = dn * dn;

    uint2 sv = h0[(size_t)node * 16 + hl];
    float2 s0 = h22f2(sv.x), s1 = h22f2(sv.y);
    float a0 = sw * s0.x, a1 = sw * s0.y, a2 = sw * s1.x, a3 = sw * s1.y;

    int beg = g_rowptr[node];
    int end = g_rowptr[node + 1];

    #pragma unroll 4
    for (int e = beg; e < end; e++) {
        int2  ed = __ldg(&g_edge[e]);
        float ww = __int_as_float(ed.y);
        uint2 hv = __ldg(&h0[(size_t)ed.x * 16 + hl]);
        float2 f0 = h22f2(hv.x), f1 = h22f2(hv.y);
        a0 += ww * f0.x;
        a1 += ww * f0.y;
        a2 += ww * f1.x;
        a3 += ww * f1.y;
    }

    float4 bv = reinterpret_cast<const float4*>(bias)[hl];
    a0 += bv.x; a1 += bv.y; a2 += bv.z; a3 += bv.w;
    if (relu) {
        a0 = fmaxf(a0, 0.f); a1 = fmaxf(a1, 0.f);
        a2 = fmaxf(a2, 0.f); a3 = fmaxf(a3, 0.f);
    }
    __half2 o0 = __floats2half2_rn(a0, a1);
    __half2 o1 = __floats2half2_rn(a2, a3);
    uint2 ov = make_uint2(*reinterpret_cast<unsigned*>(&o0),
                          *reinterpret_cast<unsigned*>(&o1));
    reinterpret_cast<uint2*>(g_h1h)[(size_t)node * 16 + hl] = ov;
}

// ---------------- fused pooling + MLP head ----------------
__global__ __launch_bounds__(256) void pool_head_kernel(
        const int* __restrict__ batch,
        const float* __restrict__ lin1_w, const float* __restrict__ lin1_b,
        const float* __restrict__ lin2_w, const float* __restrict__ lin2_b,
        const float* __restrict__ lin3_w, const float* __restrict__ lin3_b,
        float* __restrict__ out) {
    int g = blockIdx.x;
    int tid = threadIdx.x;
    __shared__ int s_se[2];

    if (tid < 2) {
        int target = g + tid;
        int lo = 0, hi = NN;
        while (lo < hi) {
            int mid = (lo + hi) >> 1;
            if (__ldg(&batch[mid]) < target) lo = mid + 1;
            else hi = mid;
        }
        s_se[tid] = lo;
    }
    __syncthreads();
    int start = s_se[0], end = s_se[1];

    int sub = tid >> 6;
    int d   = tid & 63;

    const __half* h1 = reinterpret_cast<const __half*>(g_h1h);
    float sum = 0.f, mx = -FLT_MAX;
    for (int n = start + sub; n < end; n += 4) {
        float v = __half2float(h1[(size_t)n * 64 + d]);
        sum += v;
        mx = fmaxf(mx, v);
    }

    __shared__ float ssum[4][64];
    __shared__ float smax[4][64];
    __shared__ float feat[128];
    __shared__ float s1[64];
    __shared__ float s2[64];
    __shared__ float red[64];

    ssum[sub][d] = sum;
    smax[sub][d] = mx;
    __syncthreads();

    if (tid < 64) {
        feat[d]      = ssum[0][d] + ssum[1][d] + ssum[2][d] + ssum[3][d];
        feat[64 + d] = fmaxf(fmaxf(smax[0][d], smax[1][d]),
                             fmaxf(smax[2][d], smax[3][d]));
    }
    __syncthreads();

    if (tid < 64) {
        float a = lin1_b[d];
        #pragma unroll 8
        for (int k = 0; k < 128; k++) a += feat[k] * lin1_w[k * 64 + d];
        s1[d] = fmaxf(a, 0.f);
    }
    __syncthreads();
    if (tid < 64) {
        float b = lin2_b[d];
        #pragma unroll 8
        for (int k = 0; k < 64; k++) b += s1[k] * lin2_w[k * 64 + d];
        s2[d] = fmaxf(b, 0.f);
        red[d] = s2[d] * lin3_w[d];
    }
    __syncthreads();
    if (tid < 32) {
        float v = red[tid] + red[tid + 32];
        #pragma unroll
        for (int off = 16; off > 0; off >>= 1)
            v += __shfl_down_sync(0xFFFFFFFF, v, off);
        if (tid == 0) out[g] = v + lin3_b[0];
    }
}

// ---------------- launch ----------------
#define SMEM_NEW(K)  ((K) * 256 + (K) * XT_LD * 8)

extern "C" void kernel_launch(void* const* d_in, const int* in_sizes, int n_in,
                              void* d_out, int out_size) {
    const float* x      = (const float*)d_in[0];
    const int*   ei     = (const int*)d_in[1];
    const int*   batch  = (const int*)d_in[2];
    const float* W_in   = (const float*)d_in[3];
    const float* b_in   = (const float*)d_in[4];
    const float* W_hid  = (const float*)d_in[5];
    const float* b_hid  = (const float*)d_in[6];
    const float* lin1_w = (const float*)d_in[7];
    const float* lin1_b = (const float*)d_in[8];
    const float* lin2_w = (const float*)d_in[9];
    const float* lin2_b = (const float*)d_in[10];
    const float* lin3_w = (const float*)d_in[11];
    const float* lin3_b = (const float*)d_in[12];
    float* out = (float*)d_out;

    cudaFuncSetAttribute(gemm_kernel<CINC, true>,
                         cudaFuncAttributeMaxDynamicSharedMemorySize, SMEM_NEW(CINC));
    cudaFuncSetAttribute(gemm_kernel<DD, false>,
                         cudaFuncAttributeMaxDynamicSharedMemorySize, SMEM_NEW(DD));

    const int gemm_blocks = NN / 128;
    const int agg_blocks  = (NN / 2 + 7) / 8;

    zero_deg_kernel<<<(NN + 255) / 256, 256>>>();
    count_deg_kernel<<<(EE + 255) / 256, 256>>>(ei);
    scanAB_kernel<<<NB_SCAN, 1024>>>();
    gemm_kernel<CINC, true><<<gemm_blocks, 256, SMEM_NEW(CINC)>>>(x, W_in);  // profile slot
    scanC_kernel<<<NB_SCAN, 1024>>>();
    scatter_kernel<<<(EE + 255) / 256, 256>>>(ei);

    aggregate_kernel<<<agg_blocks, 256>>>(b_in, 1);

    for (int i = 0; i < NHID; i++) {
        gemm_kernel<DD, false><<<gemm_blocks, 256, SMEM_NEW(DD)>>>(
            nullptr, W_hid + (size_t)i * DD * DD);
        aggregate_kernel<<<agg_blocks, 256>>>(b_hid + (size_t)i * DD,
                                              (i < NHID - 1) ? 1 : 0);
    }

    pool_head_kernel<<<GG, 256>>>(batch, lin1_w, lin1_b, lin2_w, lin2_b,
                                  lin3_w, lin3_b, out);
}

// round 15
// speedup vs baseline: 1.1079x; 1.1079x over previous
#include <cuda_runtime.h>
#include <cuda_fp16.h>
#include <math.h>
#include <float.h>

#define NN 80000
#define EE 1280000
#define GG 64
#define CINC 128
#define DD 64
#define NHID 5
#define NB_SCAN ((NN + 1023) / 1024)

typedef unsigned long long u64t;

__device__ __forceinline__ u64t fma2(u64t a, u64t b, u64t c) {
    u64t d;
    asm("fma.rn.f32x2 %0, %1, %2, %3;" : "=l"(d) : "l"(a), "l"(b), "l"(c));
    return d;
}
__device__ __forceinline__ u64t mul2(u64t a, u64t b) {
    u64t d;
    asm("mul.rn.f32x2 %0, %1, %2;" : "=l"(d) : "l"(a), "l"(b));
    return d;
}
__device__ __forceinline__ float2 h22f2(unsigned u) {
    return __half22float2(*reinterpret_cast<__half2*>(&u));
}

// ---------------- scratch ----------------
__device__ int     g_deg[NN];
__device__ float   g_dinv[NN];
__device__ int     g_rowptr[NN + 1];
__device__ int     g_eoff[EE];
__device__ int     g_col[EE];          // src index per CSR slot
__device__ __half2 g_h0h[NN * 32];     // GEMM output, pre-scaled by dinv[row] (fp16)
__device__ __half2 g_h1h[NN * 32];     // aggregation output (fp16)
__device__ int     g_bsum[NB_SCAN];
__device__ int     g_boff[NB_SCAN];
__device__ int     g_scan_done;

// ---------------- CSR build ----------------
__global__ void zero_deg_kernel() {
    int i = blockIdx.x * blockDim.x + threadIdx.x;
    if (i < NN) g_deg[i] = 0;
    if (i == 0) g_scan_done = 0;
}

__global__ void count_deg_kernel(const int* __restrict__ ei) {
    int e = blockIdx.x * blockDim.x + threadIdx.x;
    if (e < EE) g_eoff[e] = atomicAdd(&g_deg[ei[EE + e]], 1);
}

__global__ void scanAB_kernel() {
    __shared__ int sh[1024];
    int gid = blockIdx.x * 1024 + threadIdx.x;
    int v = (gid < NN) ? g_deg[gid] : 0;
    if (gid < NN) g_dinv[gid] = rsqrtf((float)(v + 1));
    sh[threadIdx.x] = v;
    __syncthreads();
    #pragma unroll
    for (int off = 1; off < 1024; off <<= 1) {
        int t = (threadIdx.x >= off) ? sh[threadIdx.x - off] : 0;
        __syncthreads();
        sh[threadIdx.x] += t;
        __syncthreads();
    }
    if (gid < NN) g_rowptr[gid] = sh[threadIdx.x] - v;
    if (threadIdx.x == 1023) g_bsum[blockIdx.x] = sh[1023];

    __shared__ int s_last;
    __threadfence();
    if (threadIdx.x == 0)
        s_last = (atomicAdd(&g_scan_done, 1) == NB_SCAN - 1);
    __syncthreads();
    if (s_last) {
        int t = threadIdx.x;
        int bv = (t < NB_SCAN) ? g_bsum[t] : 0;
        if (t < 128) sh[t] = bv;
        __syncthreads();
        #pragma unroll
        for (int off = 1; off < 128; off <<= 1) {
            int u = (t >= off && t < 128) ? sh[t - off] : 0;
            __syncthreads();
            if (t < 128) sh[t] += u;
            __syncthreads();
        }
        if (t < NB_SCAN) g_boff[t] = sh[t] - bv;
    }
}

__global__ void scanC_kernel() {
    int gid = blockIdx.x * 1024 + threadIdx.x;
    if (gid < NN)
        g_rowptr[gid] += g_boff[blockIdx.x];
    if (gid == 0) g_rowptr[NN] = EE;
}

__global__ void scatter_kernel(const int* __restrict__ ei) {
    int e = blockIdx.x * blockDim.x + threadIdx.x;
    if (e < EE) {
        int s = ei[e];
        int d = ei[EE + e];
        g_col[g_rowptr[d] + g_eoff[e]] = s;
    }
}

// ------ Tiled GEMM: g_h0h[N,64](fp16) = dinv[row] * (A[N,K] @ W[K,64]) ----
// 256 threads = 8 warps; warp = 16 rows x 64 cols; lane = 16 rows x 2 cols.
// smem: Ws [K][64] fp32 (lane LDS.64, conflict-free);
//       Xt [K][66 u64] row-pair packed f32x2 (uniform LDS.128 broadcast);
//       Ds [128] dinv tile.
#define XT_LD 66
template <int K, bool FROM_EXT>
__global__ __launch_bounds__(256) void gemm_kernel(const float* __restrict__ X,
                                                   const float* __restrict__ W) {
    extern __shared__ char smem_raw[];
    float* Ws = reinterpret_cast<float*>(smem_raw);
    u64t*  Xt = reinterpret_cast<u64t*>(smem_raw + (size_t)K * 256);
    float* Ds = reinterpret_cast<float*>(smem_raw + (size_t)K * 256 +
                                         (size_t)K * XT_LD * 8);

    int tid = threadIdx.x;

    // W: coalesced copy
    #pragma unroll
    for (int i = tid; i < K * 64; i += 256) Ws[i] = W[i];
    if (tid < 128) Ds[tid] = g_dinv[(size_t)blockIdx.x * 128 + tid];

    // X: load + transpose into row-pair-packed layout
    if (FROM_EXT) {
        const float* xb = X + (size_t)blockIdx.x * 128 * K;
        #pragma unroll
        for (int i = tid; i < 128 * K; i += 256) {
            int r = i / K, k = i - r * K;
            reinterpret_cast<float*>(Xt + (size_t)k * XT_LD + (r >> 1))[r & 1] = xb[i];
        }
    } else {
        const uint4* ab = reinterpret_cast<const uint4*>(g_h1h) +
                          (size_t)blockIdx.x * 128 * 8;   // 8 uint4 per 64-half row
        #pragma unroll
        for (int i = tid; i < 128 * 8; i += 256) {
            int r = i >> 3, c8 = i & 7;
            uint4 v = ab[i];
            float2 f0 = h22f2(v.x), f1 = h22f2(v.y), f2 = h22f2(v.z), f3 = h22f2(v.w);
            int k0 = c8 * 8;
            int rp = r >> 1, rb = r & 1;
            reinterpret_cast<float*>(Xt + (size_t)(k0 + 0) * XT_LD + rp)[rb] = f0.x;
            reinterpret_cast<float*>(Xt + (size_t)(k0 + 1) * XT_LD + rp)[rb] = f0.y;
            reinterpret_cast<float*>(Xt + (size_t)(k0 + 2) * XT_LD + rp)[rb] = f1.x;
            reinterpret_cast<float*>(Xt + (size_t)(k0 + 3) * XT_LD + rp)[rb] = f1.y;
            reinterpret_cast<float*>(Xt + (size_t)(k0 + 4) * XT_LD + rp)[rb] = f2.x;
            reinterpret_cast<float*>(Xt + (size_t)(k0 + 5) * XT_LD + rp)[rb] = f2.y;
            reinterpret_cast<float*>(Xt + (size_t)(k0 + 6) * XT_LD + rp)[rb] = f3.x;
            reinterpret_cast<float*>(Xt + (size_t)(k0 + 7) * XT_LD + rp)[rb] = f3.y;
        }
    }
    __syncthreads();

    int lane = tid & 31, warp = tid >> 5;

    u64t acc[16];   // acc[2*rp + c]: rp=0..7 (row pairs), c=0..1 (cols 2*lane+c)
    #pragma unroll
    for (int j = 0; j < 16; j++) acc[j] = 0ull;

    #pragma unroll 2
    for (int k = 0; k < K; k++) {
        // W: lane's two columns, contiguous 8B -> conflict-free LDS.64
        u64t w2 = *reinterpret_cast<const u64t*>(Ws + k * 64 + 2 * lane);
        unsigned wl, wh;
        asm("mov.b64 {%0, %1}, %2;" : "=r"(wl), "=r"(wh) : "l"(w2));
        u64t wd0, wd1;
        asm("mov.b64 %0, {%1, %1};" : "=l"(wd0) : "r"(wl));
        asm("mov.b64 %0, {%1, %1};" : "=l"(wd1) : "r"(wh));

        // X: 8 row pairs, uniform broadcast LDS.128 x4
        const ulonglong2* xp = reinterpret_cast<const ulonglong2*>(
            Xt + (size_t)k * XT_LD + warp * 8);
        ulonglong2 xa = xp[0], xb2 = xp[1], xc = xp[2], xd = xp[3];

        acc[0]  = fma2(xa.x,  wd0, acc[0]);  acc[1]  = fma2(xa.x,  wd1, acc[1]);
        acc[2]  = fma2(xa.y,  wd0, acc[2]);  acc[3]  = fma2(xa.y,  wd1, acc[3]);
        acc[4]  = fma2(xb2.x, wd0, acc[4]);  acc[5]  = fma2(xb2.x, wd1, acc[5]);
        acc[6]  = fma2(xb2.y, wd0, acc[6]);  acc[7]  = fma2(xb2.y, wd1, acc[7]);
        acc[8]  = fma2(xc.x,  wd0, acc[8]);  acc[9]  = fma2(xc.x,  wd1, acc[9]);
        acc[10] = fma2(xc.y,  wd0, acc[10]); acc[11] = fma2(xc.y,  wd1, acc[11]);
        acc[12] = fma2(xd.x,  wd0, acc[12]); acc[13] = fma2(xd.x,  wd1, acc[13]);
        acc[14] = fma2(xd.y,  wd0, acc[14]); acc[15] = fma2(xd.y,  wd1, acc[15]);
    }

    // epilogue: scale rows by dinv, store half2
    size_t rowbase = (size_t)blockIdx.x * 128 + warp * 16;
    #pragma unroll
    for (int rp = 0; rp < 8; rp++) {
        // pack (dinv[r0], dinv[r0+1]) and scale the row-pair accumulators
        u64t dd;
        {
            unsigned dlo = __float_as_uint(Ds[warp * 16 + 2 * rp]);
            unsigned dhi = __float_as_uint(Ds[warp * 16 + 2 * rp + 1]);
            asm("mov.b64 %0, {%1, %2};" : "=l"(dd) : "r"(dlo), "r"(dhi));
        }
        u64t s0 = mul2(acc[2 * rp], dd);
        u64t s1 = mul2(acc[2 * rp + 1], dd);
        unsigned l0, h0, l1, h1;
        asm("mov.b64 {%0, %1}, %2;" : "=r"(l0), "=r"(h0) : "l"(s0));
        asm("mov.b64 {%0, %1}, %2;" : "=r"(l1), "=r"(h1) : "l"(s1));
        size_t r0 = rowbase + 2 * rp;
        g_h0h[r0 * 32 + lane] =
            __floats2half2_rn(__uint_as_float(l0), __uint_as_float(l1));
        g_h0h[(r0 + 1) * 32 + lane] =
            __floats2half2_rn(__uint_as_float(h0), __uint_as_float(h1));
    }
}

// ------ aggregation: HALF-warp per node, pure-sum gather -------------------
// out[d] = dinv[d] * (h'[d] + sum_{s in N(d)} h'[s]) + bias   (h' pre-scaled)
__global__ void aggregate_kernel(const float* __restrict__ bias, int relu) {
    int warp = blockIdx.x * (blockDim.x >> 5) + (threadIdx.x >> 5);
    int half = (threadIdx.x >> 4) & 1;
    int hl   = threadIdx.x & 15;
    int node = warp * 2 + half;
    if (node >= NN) return;

    const uint2* h0 = reinterpret_cast<const uint2*>(g_h0h);

    uint2 sv = h0[(size_t)node * 16 + hl];
    float2 s0 = h22f2(sv.x), s1 = h22f2(sv.y);
    float a0 = s0.x, a1 = s0.y, a2 = s1.x, a3 = s1.y;

    int beg = g_rowptr[node];
    int end = g_rowptr[node + 1];

    #pragma unroll 4
    for (int e = beg; e < end; e++) {
        int s = __ldg(&g_col[e]);
        uint2 hv = __ldg(&h0[(size_t)s * 16 + hl]);
        float2 f0 = h22f2(hv.x), f1 = h22f2(hv.y);
        a0 += f0.x;
        a1 += f0.y;
        a2 += f1.x;
        a3 += f1.y;
    }

    float dn = g_dinv[node];
    float4 bv = reinterpret_cast<const float4*>(bias)[hl];
    a0 = a0 * dn + bv.x;
    a1 = a1 * dn + bv.y;
    a2 = a2 * dn + bv.z;
    a3 = a3 * dn + bv.w;
    if (relu) {
        a0 = fmaxf(a0, 0.f); a1 = fmaxf(a1, 0.f);
        a2 = fmaxf(a2, 0.f); a3 = fmaxf(a3, 0.f);
    }
    __half2 o0 = __floats2half2_rn(a0, a1);
    __half2 o1 = __floats2half2_rn(a2, a3);
    uint2 ov = make_uint2(*reinterpret_cast<unsigned*>(&o0),
                          *reinterpret_cast<unsigned*>(&o1));
    reinterpret_cast<uint2*>(g_h1h)[(size_t)node * 16 + hl] = ov;
}

// ---------------- fused pooling + MLP head ----------------
__global__ __launch_bounds__(256) void pool_head_kernel(
        const int* __restrict__ batch,
        const float* __restrict__ lin1_w, const float* __restrict__ lin1_b,
        const float* __restrict__ lin2_w, const float* __restrict__ lin2_b,
        const float* __restrict__ lin3_w, const float* __restrict__ lin3_b,
        float* __restrict__ out) {
    int g = blockIdx.x;
    int tid = threadIdx.x;
    __shared__ int s_se[2];

    if (tid < 2) {
        int target = g + tid;
        int lo = 0, hi = NN;
        while (lo < hi) {
            int mid = (lo + hi) >> 1;
            if (__ldg(&batch[mid]) < target) lo = mid + 1;
            else hi = mid;
        }
        s_se[tid] = lo;
    }
    __syncthreads();
    int start = s_se[0], end = s_se[1];

    int sub = tid >> 6;
    int d   = tid & 63;

    const __half* h1 = reinterpret_cast<const __half*>(g_h1h);
    float sum = 0.f, mx = -FLT_MAX;
    for (int n = start + sub; n < end; n += 4) {
        float v = __half2float(h1[(size_t)n * 64 + d]);
        sum += v;
        mx = fmaxf(mx, v);
    }

    __shared__ float ssum[4][64];
    __shared__ float smax[4][64];
    __shared__ float feat[128];
    __shared__ float s1[64];
    __shared__ float s2[64];
    __shared__ float red[64];

    ssum[sub][d] = sum;
    smax[sub][d] = mx;
    __syncthreads();

    if (tid < 64) {
        feat[d]      = ssum[0][d] + ssum[1][d] + ssum[2][d] + ssum[3][d];
        feat[64 + d] = fmaxf(fmaxf(smax[0][d], smax[1][d]),
                             fmaxf(smax[2][d], smax[3][d]));
    }
    __syncthreads();

    if (tid < 64) {
        float a = lin1_b[d];
        #pragma unroll 8
        for (int k = 0; k < 128; k++) a += feat[k] * lin1_w[k * 64 + d];
        s1[d] = fmaxf(a, 0.f);
    }
    __syncthreads();
    if (tid < 64) {
        float b = lin2_b[d];
        #pragma unroll 8
        for (int k = 0; k < 64; k++) b += s1[k] * lin2_w[k * 64 + d];
        s2[d] = fmaxf(b, 0.f);
        red[d] = s2[d] * lin3_w[d];
    }
    __syncthreads();
    if (tid < 32) {
        float v = red[tid] + red[tid + 32];
        #pragma unroll
        for (int off = 16; off > 0; off >>= 1)
            v += __shfl_down_sync(0xFFFFFFFF, v, off);
        if (tid == 0) out[g] = v + lin3_b[0];
    }
}

// ---------------- launch ----------------
#define SMEM_NEW(K)  ((K) * 256 + (K) * XT_LD * 8 + 512)

extern "C" void kernel_launch(void* const* d_in, const int* in_sizes, int n_in,
                              void* d_out, int out_size) {
    const float* x      = (const float*)d_in[0];
    const int*   ei     = (const int*)d_in[1];
    const int*   batch  = (const int*)d_in[2];
    const float* W_in   = (const float*)d_in[3];
    const float* b_in   = (const float*)d_in[4];
    const float* W_hid  = (const float*)d_in[5];
    const float* b_hid  = (const float*)d_in[6];
    const float* lin1_w = (const float*)d_in[7];
    const float* lin1_b = (const float*)d_in[8];
    const float* lin2_w = (const float*)d_in[9];
    const float* lin2_b = (const float*)d_in[10];
    const float* lin3_w = (const float*)d_in[11];
    const float* lin3_b = (const float*)d_in[12];
    float* out = (float*)d_out;

    cudaFuncSetAttribute(gemm_kernel<CINC, true>,
                         cudaFuncAttributeMaxDynamicSharedMemorySize, SMEM_NEW(CINC));
    cudaFuncSetAttribute(gemm_kernel<DD, false>,
                         cudaFuncAttributeMaxDynamicSharedMemorySize, SMEM_NEW(DD));

    const int gemm_blocks = NN / 128;
    const int agg_blocks  = (NN / 2 + 7) / 8;

    zero_deg_kernel<<<(NN + 255) / 256, 256>>>();
    count_deg_kernel<<<(EE + 255) / 256, 256>>>(ei);
    scanAB_kernel<<<NB_SCAN, 1024>>>();
    gemm_kernel<CINC, true><<<gemm_blocks, 256, SMEM_NEW(CINC)>>>(x, W_in);  // profile slot
    scanC_kernel<<<NB_SCAN, 1024>>>();
    scatter_kernel<<<(EE + 255) / 256, 256>>>(ei);

    aggregate_kernel<<<agg_blocks, 256>>>(b_in, 1);

    for (int i = 0; i < NHID; i++) {
        gemm_kernel<DD, false><<<gemm_blocks, 256, SMEM_NEW(DD)>>>(
            nullptr, W_hid + (size_t)i * DD * DD);
        aggregate_kernel<<<agg_blocks, 256>>>(b_hid + (size_t)i * DD,
                                              (i < NHID - 1) ? 1 : 0);
    }

    pool_head_kernel<<<GG, 256>>>(batch, lin1_w, lin1_b, lin2_w, lin2_b,
                                  lin3_w, lin3_b, out);
}

// round 16
// speedup vs baseline: 1.1161x; 1.0073x over previous
#include <cuda_runtime.h>
#include <cuda_fp16.h>
#include <math.h>
#include <float.h>

#define NN 80000
#define EE 1280000
#define GG 64
#define CINC 128
#define DD 64
#define NHID 5
#define NB_SCAN ((NN + 1023) / 1024)

typedef unsigned long long u64t;

__device__ __forceinline__ u64t fma2(u64t a, u64t b, u64t c) {
    u64t d;
    asm("fma.rn.f32x2 %0, %1, %2, %3;" : "=l"(d) : "l"(a), "l"(b), "l"(c));
    return d;
}
__device__ __forceinline__ u64t mul2(u64t a, u64t b) {
    u64t d;
    asm("mul.rn.f32x2 %0, %1, %2;" : "=l"(d) : "l"(a), "l"(b));
    return d;
}
__device__ __forceinline__ float2 h22f2(unsigned u) {
    return __half22float2(*reinterpret_cast<__half2*>(&u));
}

// ---------------- scratch ----------------
__device__ int     g_deg[NN];
__device__ float   g_dinv[NN];
__device__ int     g_rowptr[NN + 1];
__device__ int     g_eoff[EE];
__device__ int     g_col[EE];          // src index per CSR slot
__device__ __half2 g_h0h[NN * 32];     // GEMM output (fp16, gather source)
__device__ __half2 g_h1h[NN * 32];     // aggregation output (fp16)
__device__ int     g_bsum[NB_SCAN];
__device__ int     g_boff[NB_SCAN];
__device__ int     g_scan_done;

// ---------------- CSR build ----------------
__global__ void zero_deg_kernel() {
    int i = blockIdx.x * blockDim.x + threadIdx.x;
    if (i < NN) g_deg[i] = 0;
    if (i == 0) g_scan_done = 0;
}

__global__ void count_deg_kernel(const int* __restrict__ ei) {
    int e = blockIdx.x * blockDim.x + threadIdx.x;
    if (e < EE) g_eoff[e] = atomicAdd(&g_deg[ei[EE + e]], 1);
}

__global__ void scanAB_kernel() {
    __shared__ int sh[1024];
    int gid = blockIdx.x * 1024 + threadIdx.x;
    int v = (gid < NN) ? g_deg[gid] : 0;
    if (gid < NN) g_dinv[gid] = rsqrtf((float)(v + 1));
    sh[threadIdx.x] = v;
    __syncthreads();
    #pragma unroll
    for (int off = 1; off < 1024; off <<= 1) {
        int t = (threadIdx.x >= off) ? sh[threadIdx.x - off] : 0;
        __syncthreads();
        sh[threadIdx.x] += t;
        __syncthreads();
    }
    if (gid < NN) g_rowptr[gid] = sh[threadIdx.x] - v;
    if (threadIdx.x == 1023) g_bsum[blockIdx.x] = sh[1023];

    __shared__ int s_last;
    __threadfence();
    if (threadIdx.x == 0)
        s_last = (atomicAdd(&g_scan_done, 1) == NB_SCAN - 1);
    __syncthreads();
    if (s_last) {
        int t = threadIdx.x;
        int bv = (t < NB_SCAN) ? g_bsum[t] : 0;
        if (t < 128) sh[t] = bv;
        __syncthreads();
        #pragma unroll
        for (int off = 1; off < 128; off <<= 1) {
            int u = (t >= off && t < 128) ? sh[t - off] : 0;
            __syncthreads();
            if (t < 128) sh[t] += u;
            __syncthreads();
        }
        if (t < NB_SCAN) g_boff[t] = sh[t] - bv;
    }
}

__global__ void scanC_kernel() {
    int gid = blockIdx.x * 1024 + threadIdx.x;
    if (gid < NN)
        g_rowptr[gid] += g_boff[blockIdx.x];
    if (gid == 0) g_rowptr[NN] = EE;
}

__global__ void scatter_kernel(const int* __restrict__ ei) {
    int e = blockIdx.x * blockDim.x + threadIdx.x;
    if (e < EE) {
        int s = ei[e];
        int d = ei[EE + e];
        g_col[g_rowptr[d] + g_eoff[e]] = s;
    }
}

// ------ Tiled GEMM: g_h0h[N,64](fp16) = [dinv?] * (A[N,K] @ W[K,64]) ------
#define XT_LD 66
template <int K, bool FROM_EXT, bool SCALE>
__global__ __launch_bounds__(256) void gemm_kernel(const float* __restrict__ X,
                                                   const float* __restrict__ W) {
    extern __shared__ char smem_raw[];
    float* Ws = reinterpret_cast<float*>(smem_raw);
    u64t*  Xt = reinterpret_cast<u64t*>(smem_raw + (size_t)K * 256);
    float* Ds = reinterpret_cast<float*>(smem_raw + (size_t)K * 256 +
                                         (size_t)K * XT_LD * 8);

    int tid = threadIdx.x;

    #pragma unroll
    for (int i = tid; i < K * 64; i += 256) Ws[i] = W[i];
    if (SCALE && tid < 128) Ds[tid] = g_dinv[(size_t)blockIdx.x * 128 + tid];

    if (FROM_EXT) {
        const float* xb = X + (size_t)blockIdx.x * 128 * K;
        #pragma unroll
        for (int i = tid; i < 128 * K; i += 256) {
            int r = i / K, k = i - r * K;
            reinterpret_cast<float*>(Xt + (size_t)k * XT_LD + (r >> 1))[r & 1] = xb[i];
        }
    } else {
        const uint4* ab = reinterpret_cast<const uint4*>(g_h1h) +
                          (size_t)blockIdx.x * 128 * 8;
        #pragma unroll
        for (int i = tid; i < 128 * 8; i += 256) {
            int r = i >> 3, c8 = i & 7;
            uint4 v = ab[i];
            float2 f0 = h22f2(v.x), f1 = h22f2(v.y), f2 = h22f2(v.z), f3 = h22f2(v.w);
            int k0 = c8 * 8;
            int rp = r >> 1, rb = r & 1;
            reinterpret_cast<float*>(Xt + (size_t)(k0 + 0) * XT_LD + rp)[rb] = f0.x;
            reinterpret_cast<float*>(Xt + (size_t)(k0 + 1) * XT_LD + rp)[rb] = f0.y;
            reinterpret_cast<float*>(Xt + (size_t)(k0 + 2) * XT_LD + rp)[rb] = f1.x;
            reinterpret_cast<float*>(Xt + (size_t)(k0 + 3) * XT_LD + rp)[rb] = f1.y;
            reinterpret_cast<float*>(Xt + (size_t)(k0 + 4) * XT_LD + rp)[rb] = f2.x;
            reinterpret_cast<float*>(Xt + (size_t)(k0 + 5) * XT_LD + rp)[rb] = f2.y;
            reinterpret_cast<float*>(Xt + (size_t)(k0 + 6) * XT_LD + rp)[rb] = f3.x;
            reinterpret_cast<float*>(Xt + (size_t)(k0 + 7) * XT_LD + rp)[rb] = f3.y;
        }
    }
    __syncthreads();

    int lane = tid & 31, warp = tid >> 5;

    u64t acc[16];
    #pragma unroll
    for (int j = 0; j < 16; j++) acc[j] = 0ull;

    #pragma unroll 2
    for (int k = 0; k < K; k++) {
        u64t w2 = *reinterpret_cast<const u64t*>(Ws + k * 64 + 2 * lane);
        unsigned wl, wh;
        asm("mov.b64 {%0, %1}, %2;" : "=r"(wl), "=r"(wh) : "l"(w2));
        u64t wd0, wd1;
        asm("mov.b64 %0, {%1, %1};" : "=l"(wd0) : "r"(wl));
        asm("mov.b64 %0, {%1, %1};" : "=l"(wd1) : "r"(wh));

        const ulonglong2* xp = reinterpret_cast<const ulonglong2*>(
            Xt + (size_t)k * XT_LD + warp * 8);
        ulonglong2 xa = xp[0], xb2 = xp[1], xc = xp[2], xd = xp[3];

        acc[0]  = fma2(xa.x,  wd0, acc[0]);  acc[1]  = fma2(xa.x,  wd1, acc[1]);
        acc[2]  = fma2(xa.y,  wd0, acc[2]);  acc[3]  = fma2(xa.y,  wd1, acc[3]);
        acc[4]  = fma2(xb2.x, wd0, acc[4]);  acc[5]  = fma2(xb2.x, wd1, acc[5]);
        acc[6]  = fma2(xb2.y, wd0, acc[6]);  acc[7]  = fma2(xb2.y, wd1, acc[7]);
        acc[8]  = fma2(xc.x,  wd0, acc[8]);  acc[9]  = fma2(xc.x,  wd1, acc[9]);
        acc[10] = fma2(xc.y,  wd0, acc[10]); acc[11] = fma2(xc.y,  wd1, acc[11]);
        acc[12] = fma2(xd.x,  wd0, acc[12]); acc[13] = fma2(xd.x,  wd1, acc[13]);
        acc[14] = fma2(xd.y,  wd0, acc[14]); acc[15] = fma2(xd.y,  wd1, acc[15]);
    }

    size_t rowbase = (size_t)blockIdx.x * 128 + warp * 16;
    #pragma unroll
    for (int rp = 0; rp < 8; rp++) {
        u64t s0 = acc[2 * rp], s1 = acc[2 * rp + 1];
        if (SCALE) {
            u64t dd;
            unsigned dlo = __float_as_uint(Ds[warp * 16 + 2 * rp]);
            unsigned dhi = __float_as_uint(Ds[warp * 16 + 2 * rp + 1]);
            asm("mov.b64 %0, {%1, %2};" : "=l"(dd) : "r"(dlo), "r"(dhi));
            s0 = mul2(s0, dd);
            s1 = mul2(s1, dd);
        }
        unsigned l0, h0, l1, h1;
        asm("mov.b64 {%0, %1}, %2;" : "=r"(l0), "=r"(h0) : "l"(s0));
        asm("mov.b64 {%0, %1}, %2;" : "=r"(l1), "=r"(h1) : "l"(s1));
        size_t r0 = rowbase + 2 * rp;
        g_h0h[r0 * 32 + lane] =
            __floats2half2_rn(__uint_as_float(l0), __uint_as_float(l1));
        g_h0h[(r0 + 1) * 32 + lane] =
            __floats2half2_rn(__uint_as_float(h0), __uint_as_float(h1));
    }
}

// ------ aggregation (hidden layers): pure-sum gather ----------------------
__global__ void aggregate_kernel(const float* __restrict__ bias, int relu) {
    int warp = blockIdx.x * (blockDim.x >> 5) + (threadIdx.x >> 5);
    int half = (threadIdx.x >> 4) & 1;
    int hl   = threadIdx.x & 15;
    int node = warp * 2 + half;
    if (node >= NN) return;

    const uint2* h0 = reinterpret_cast<const uint2*>(g_h0h);

    uint2 sv = h0[(size_t)node * 16 + hl];
    float2 s0 = h22f2(sv.x), s1 = h22f2(sv.y);
    float a0 = s0.x, a1 = s0.y, a2 = s1.x, a3 = s1.y;

    int beg = g_rowptr[node];
    int end = g_rowptr[node + 1];

    #pragma unroll 4
    for (int e = beg; e < end; e++) {
        int s = __ldg(&g_col[e]);
        uint2 hv = __ldg(&h0[(size_t)s * 16 + hl]);
        float2 f0 = h22f2(hv.x), f1 = h22f2(hv.y);
        a0 += f0.x;
        a1 += f0.y;
        a2 += f1.x;
        a3 += f1.y;
    }

    float dn = g_dinv[node];
    float4 bv = reinterpret_cast<const float4*>(bias)[hl];
    a0 = a0 * dn + bv.x;
    a1 = a1 * dn + bv.y;
    a2 = a2 * dn + bv.z;
    a3 = a3 * dn + bv.w;
    if (relu) {
        a0 = fmaxf(a0, 0.f); a1 = fmaxf(a1, 0.f);
        a2 = fmaxf(a2, 0.f); a3 = fmaxf(a3, 0.f);
    }
    __half2 o0 = __floats2half2_rn(a0, a1);
    __half2 o1 = __floats2half2_rn(a2, a3);
    uint2 ov = make_uint2(*reinterpret_cast<unsigned*>(&o0),
                          *reinterpret_cast<unsigned*>(&o1));
    reinterpret_cast<uint2*>(g_h1h)[(size_t)node * 16 + hl] = ov;
}

// ------ aggregation (layer 0): h0 unscaled, gather dinv[src] per edge -----
__global__ void aggregate0_kernel(const float* __restrict__ bias) {
    int warp = blockIdx.x * (blockDim.x >> 5) + (threadIdx.x >> 5);
    int half = (threadIdx.x >> 4) & 1;
    int hl   = threadIdx.x & 15;
    int node = warp * 2 + half;
    if (node >= NN) return;

    const uint2* h0 = reinterpret_cast<const uint2*>(g_h0h);

    float dn = g_dinv[node];
    uint2 sv = h0[(size_t)node * 16 + hl];
    float2 s0 = h22f2(sv.x), s1 = h22f2(sv.y);
    // self term carries one dinv factor here; outer dinv applied at the end
    float a0 = dn * s0.x, a1 = dn * s0.y, a2 = dn * s1.x, a3 = dn * s1.y;

    int beg = g_rowptr[node];
    int end = g_rowptr[node + 1];

    #pragma unroll 4
    for (int e = beg; e < end; e++) {
        int s = __ldg(&g_col[e]);
        float ds = __ldg(&g_dinv[s]);
        uint2 hv = __ldg(&h0[(size_t)s * 16 + hl]);
        float2 f0 = h22f2(hv.x), f1 = h22f2(hv.y);
        a0 += ds * f0.x;
        a1 += ds * f0.y;
        a2 += ds * f1.x;
        a3 += ds * f1.y;
    }

    float4 bv = reinterpret_cast<const float4*>(bias)[hl];
    a0 = fmaxf(a0 * dn + bv.x, 0.f);
    a1 = fmaxf(a1 * dn + bv.y, 0.f);
    a2 = fmaxf(a2 * dn + bv.z, 0.f);
    a3 = fmaxf(a3 * dn + bv.w, 0.f);
    __half2 o0 = __floats2half2_rn(a0, a1);
    __half2 o1 = __floats2half2_rn(a2, a3);
    uint2 ov = make_uint2(*reinterpret_cast<unsigned*>(&o0),
                          *reinterpret_cast<unsigned*>(&o1));
    reinterpret_cast<uint2*>(g_h1h)[(size_t)node * 16 + hl] = ov;
}

// ---------------- fused pooling + MLP head ----------------
__global__ __launch_bounds__(256) void pool_head_kernel(
        const int* __restrict__ batch,
        const float* __restrict__ lin1_w, const float* __restrict__ lin1_b,
        const float* __restrict__ lin2_w, const float* __restrict__ lin2_b,
        const float* __restrict__ lin3_w, const float* __restrict__ lin3_b,
        float* __restrict__ out) {
    int g = blockIdx.x;
    int tid = threadIdx.x;
    __shared__ int s_se[2];

    if (tid < 2) {
        int target = g + tid;
        int lo = 0, hi = NN;
        while (lo < hi) {
            int mid = (lo + hi) >> 1;
            if (__ldg(&batch[mid]) < target) lo = mid + 1;
            else hi = mid;
        }
        s_se[tid] = lo;
    }
    __syncthreads();
    int start = s_se[0], end = s_se[1];

    int sub = tid >> 6;
    int d   = tid & 63;

    const __half* h1 = reinterpret_cast<const __half*>(g_h1h);
    float sum = 0.f, mx = -FLT_MAX;
    for (int n = start + sub; n < end; n += 4) {
        float v = __half2float(h1[(size_t)n * 64 + d]);
        sum += v;
        mx = fmaxf(mx, v);
    }

    __shared__ float ssum[4][64];
    __shared__ float smax[4][64];
    __shared__ float feat[128];
    __shared__ float s1[64];
    __shared__ float s2[64];
    __shared__ float red[64];

    ssum[sub][d] = sum;
    smax[sub][d] = mx;
    __syncthreads();

    if (tid < 64) {
        feat[d]      = ssum[0][d] + ssum[1][d] + ssum[2][d] + ssum[3][d];
        feat[64 + d] = fmaxf(fmaxf(smax[0][d], smax[1][d]),
                             fmaxf(smax[2][d], smax[3][d]));
    }
    __syncthreads();

    if (tid < 64) {
        float a = lin1_b[d];
        #pragma unroll 8
        for (int k = 0; k < 128; k++) a += feat[k] * lin1_w[k * 64 + d];
        s1[d] = fmaxf(a, 0.f);
    }
    __syncthreads();
    if (tid < 64) {
        float b = lin2_b[d];
        #pragma unroll 8
        for (int k = 0; k < 64; k++) b += s1[k] * lin2_w[k * 64 + d];
        s2[d] = fmaxf(b, 0.f);
        red[d] = s2[d] * lin3_w[d];
    }
    __syncthreads();
    if (tid < 32) {
        float v = red[tid] + red[tid + 32];
        #pragma unroll
        for (int off = 16; off > 0; off >>= 1)
            v += __shfl_down_sync(0xFFFFFFFF, v, off);
        if (tid == 0) out[g] = v + lin3_b[0];
    }
}

// ---------------- launch ----------------
#define SMEM_NEW(K)  ((K) * 256 + (K) * XT_LD * 8 + 512)

extern "C" void kernel_launch(void* const* d_in, const int* in_sizes, int n_in,
                              void* d_out, int out_size) {
    const float* x      = (const float*)d_in[0];
    const int*   ei     = (const int*)d_in[1];
    const int*   batch  = (const int*)d_in[2];
    const float* W_in   = (const float*)d_in[3];
    const float* b_in   = (const float*)d_in[4];
    const float* W_hid  = (const float*)d_in[5];
    const float* b_hid  = (const float*)d_in[6];
    const float* lin1_w = (const float*)d_in[7];
    const float* lin1_b = (const float*)d_in[8];
    const float* lin2_w = (const float*)d_in[9];
    const float* lin2_b = (const float*)d_in[10];
    const float* lin3_w = (const float*)d_in[11];
    const float* lin3_b = (const float*)d_in[12];
    float* out = (float*)d_out;

    // one-time host-side resources (no device memory)
    static cudaStream_t s2 = nullptr;
    static cudaEvent_t evFork = nullptr, evCSR = nullptr;
    if (s2 == nullptr) {
        cudaStreamCreateWithFlags(&s2, cudaStreamNonBlocking);
        cudaEventCreateWithFlags(&evFork, cudaEventDisableTiming);
        cudaEventCreateWithFlags(&evCSR, cudaEventDisableTiming);
        cudaFuncSetAttribute(gemm_kernel<CINC, true, false>,
                             cudaFuncAttributeMaxDynamicSharedMemorySize, SMEM_NEW(CINC));
        cudaFuncSetAttribute(gemm_kernel<DD, false, true>,
                             cudaFuncAttributeMaxDynamicSharedMemorySize, SMEM_NEW(DD));
    }

    const int gemm_blocks = NN / 128;
    const int agg_blocks  = (NN / 2 + 7) / 8;

    // fork: CSR chain on s2, input GEMM on main — independent
    cudaEventRecord(evFork, 0);
    cudaStreamWaitEvent(s2, evFork, 0);

    zero_deg_kernel<<<(NN + 255) / 256, 256, 0, s2>>>();
    count_deg_kernel<<<(EE + 255) / 256, 256, 0, s2>>>(ei);
    scanAB_kernel<<<NB_SCAN, 1024, 0, s2>>>();
    scanC_kernel<<<NB_SCAN, 1024, 0, s2>>>();
    scatter_kernel<<<(EE + 255) / 256, 256, 0, s2>>>(ei);
    cudaEventRecord(evCSR, s2);

    gemm_kernel<CINC, true, false><<<gemm_blocks, 256, SMEM_NEW(CINC)>>>(x, W_in);

    // join: layer-0 aggregation needs both
    cudaStreamWaitEvent(0, evCSR, 0);
    aggregate0_kernel<<<agg_blocks, 256>>>(b_in);

    for (int i = 0; i < NHID; i++) {
        gemm_kernel<DD, false, true><<<gemm_blocks, 256, SMEM_NEW(DD)>>>(
            nullptr, W_hid + (size_t)i * DD * DD);
        aggregate_kernel<<<agg_blocks, 256>>>(b_hid + (size_t)i * DD,
                                              (i < NHID - 1) ? 1 : 0);
    }

    pool_head_kernel<<<GG, 256>>>(batch, lin1_w, lin1_b, lin2_w, lin2_b,
                                  lin3_w, lin3_b, out);
}